// round 1
// baseline (speedup 1.0000x reference)
#include <cuda_runtime.h>
#include <cstdint>

// Segmented polynomial product:
//   out[idx_out[e], k*32+u] += sum_{i,j} C[i][j][k] * a[idx_a[e], i*32+u] * b[e, j*32+u]
// SA=4, SB=3, SC=4, U=32, k=(i+j)%4, C=0.1*(i+1)+0.01*(j+1)
//
// Mapping: 8 lanes per edge, each lane owns 4 consecutive u (float4 lane).
// Scatter uses sm_90+ vector reduction red.global.add.v4.f32 (4x fewer atomic ops).

#define U_EXT 32
#define SA 4
#define SB 3
#define SC 4

__global__ void zero_out_kernel(float4* __restrict__ out, int n4) {
    int i = blockIdx.x * blockDim.x + threadIdx.x;
    if (i < n4) out[i] = make_float4(0.f, 0.f, 0.f, 0.f);
}

__device__ __forceinline__ void red_add_v4(float* p, float4 v) {
    asm volatile("red.global.add.v4.f32 [%0], {%1,%2,%3,%4};"
                 :: "l"(p), "f"(v.x), "f"(v.y), "f"(v.z), "f"(v.w)
                 : "memory");
}

__global__ void __launch_bounds__(256)
sptp_kernel(const float* __restrict__ a,
            const float* __restrict__ b,
            const int*   __restrict__ idx_a,
            const int*   __restrict__ idx_out,
            float*       __restrict__ out,
            int E) {
    int t = blockIdx.x * blockDim.x + threadIdx.x;
    int e = t >> 3;              // 8 lanes per edge
    if (e >= E) return;
    int u0 = (t & 7) * 4;        // this lane's 4 consecutive u values

    int ia = idx_a[e];
    int io = idx_out[e];

    // Gather a segments: row of 128 floats, segment i at offset i*32.
    const float4* ap = reinterpret_cast<const float4*>(a + (long long)ia * (SA * U_EXT) + u0);
    float4 av[SA];
#pragma unroll
    for (int i = 0; i < SA; i++) av[i] = ap[i * (U_EXT / 4)];

    // Stream b segments: row of 96 floats.
    const float4* bp = reinterpret_cast<const float4*>(b + (long long)e * (SB * U_EXT) + u0);
    float4 bv[SB];
#pragma unroll
    for (int j = 0; j < SB; j++) bv[j] = bp[j * (U_EXT / 4)];

    float4 acc[SC];
#pragma unroll
    for (int k = 0; k < SC; k++) acc[k] = make_float4(0.f, 0.f, 0.f, 0.f);

#pragma unroll
    for (int i = 0; i < SA; i++) {
#pragma unroll
        for (int j = 0; j < SB; j++) {
            const int k = (i + j) & 3;          // (i+j) % SC, SC=4
            const float c = 0.1f * (i + 1) + 0.01f * (j + 1);
            acc[k].x = fmaf(c, av[i].x * bv[j].x, acc[k].x);
            acc[k].y = fmaf(c, av[i].y * bv[j].y, acc[k].y);
            acc[k].z = fmaf(c, av[i].z * bv[j].z, acc[k].z);
            acc[k].w = fmaf(c, av[i].w * bv[j].w, acc[k].w);
        }
    }

    float* op = out + (long long)io * (SC * U_EXT) + u0;
#pragma unroll
    for (int k = 0; k < SC; k++) red_add_v4(op + k * U_EXT, acc[k]);
}

extern "C" void kernel_launch(void* const* d_in, const int* in_sizes, int n_in,
                              void* d_out, int out_size) {
    const float* a       = (const float*)d_in[0];
    const float* b       = (const float*)d_in[1];
    const int*   idx_a   = (const int*)d_in[2];
    const int*   idx_out = (const int*)d_in[3];
    float*       out     = (float*)d_out;

    const int E = in_sizes[2];          // idx_a element count == number of edges

    // Zero the poisoned output buffer (scatter-add target).
    int n4 = out_size / 4;              // out_size = M * 128, divisible by 4
    zero_out_kernel<<<(n4 + 255) / 256, 256>>>((float4*)out, n4);

    // Main segmented tensor-product kernel: 8 threads per edge.
    long long threads = (long long)E * 8;
    int grid = (int)((threads + 255) / 256);
    sptp_kernel<<<grid, 256>>>(a, b, idx_a, idx_out, out, E);
}

// round 2
// speedup vs baseline: 1.2135x; 1.2135x over previous
#include <cuda_runtime.h>
#include <cstdint>

// Segmented polynomial product:
//   out[idx_out[e], k*32+u] += sum_{i,j} C[i][j][k] * a[idx_a[e], i*32+u] * b[e, j*32+u]
// SA=4, SB=3, SC=4, U=32, k=(i+j)%4, C=0.1*(i+1)+0.01*(j+1)
//
// Mapping: 8 lanes per edge, each lane owns 4 consecutive u (float4 lane).
// Scatter uses red.global.add.v4.f32.
//
// R2 change: streaming (evict-first) loads for b and idx so the 384MB b stream
// does not evict the L2-resident a gather set (51MB) and dirty out lines (51MB).

#define U_EXT 32
#define SA 4
#define SB 3
#define SC 4

__global__ void zero_out_kernel(float4* __restrict__ out, int n4) {
    int i = blockIdx.x * blockDim.x + threadIdx.x;
    if (i < n4) out[i] = make_float4(0.f, 0.f, 0.f, 0.f);
}

__device__ __forceinline__ void red_add_v4(float* p, float4 v) {
    asm volatile("red.global.add.v4.f32 [%0], {%1,%2,%3,%4};"
                 :: "l"(p), "f"(v.x), "f"(v.y), "f"(v.z), "f"(v.w)
                 : "memory");
}

// Streaming (evict-first) float4 load: keep one-shot data out of L2's LRU set.
__device__ __forceinline__ float4 ldcs_f4(const float4* p) {
    float4 v;
    asm volatile("ld.global.cs.v4.f32 {%0,%1,%2,%3}, [%4];"
                 : "=f"(v.x), "=f"(v.y), "=f"(v.z), "=f"(v.w)
                 : "l"(p));
    return v;
}

__device__ __forceinline__ int ldcs_i32(const int* p) {
    int v;
    asm volatile("ld.global.cs.b32 %0, [%1];" : "=r"(v) : "l"(p));
    return v;
}

__global__ void __launch_bounds__(256)
sptp_kernel(const float* __restrict__ a,
            const float* __restrict__ b,
            const int*   __restrict__ idx_a,
            const int*   __restrict__ idx_out,
            float*       __restrict__ out,
            int E) {
    int t = blockIdx.x * blockDim.x + threadIdx.x;
    int e = t >> 3;              // 8 lanes per edge
    if (e >= E) return;
    int u0 = (t & 7) * 4;        // this lane's 4 consecutive u values

    int ia = ldcs_i32(idx_a + e);
    int io = ldcs_i32(idx_out + e);

    // Stream b segments (read-once): evict-first loads.
    const float4* bp = reinterpret_cast<const float4*>(b + (long long)e * (SB * U_EXT) + u0);
    float4 bv[SB];
#pragma unroll
    for (int j = 0; j < SB; j++) bv[j] = ldcs_f4(bp + j * (U_EXT / 4));

    // Gather a segments (hot, ~10x reuse): default caching, stays in L2.
    const float4* ap = reinterpret_cast<const float4*>(a + (long long)ia * (SA * U_EXT) + u0);
    float4 av[SA];
#pragma unroll
    for (int i = 0; i < SA; i++) av[i] = __ldg(ap + i * (U_EXT / 4));

    float4 acc[SC];
#pragma unroll
    for (int k = 0; k < SC; k++) acc[k] = make_float4(0.f, 0.f, 0.f, 0.f);

#pragma unroll
    for (int i = 0; i < SA; i++) {
#pragma unroll
        for (int j = 0; j < SB; j++) {
            const int k = (i + j) & 3;          // (i+j) % SC, SC=4
            const float c = 0.1f * (i + 1) + 0.01f * (j + 1);
            acc[k].x = fmaf(c, av[i].x * bv[j].x, acc[k].x);
            acc[k].y = fmaf(c, av[i].y * bv[j].y, acc[k].y);
            acc[k].z = fmaf(c, av[i].z * bv[j].z, acc[k].z);
            acc[k].w = fmaf(c, av[i].w * bv[j].w, acc[k].w);
        }
    }

    float* op = out + (long long)io * (SC * U_EXT) + u0;
#pragma unroll
    for (int k = 0; k < SC; k++) red_add_v4(op + k * U_EXT, acc[k]);
}

extern "C" void kernel_launch(void* const* d_in, const int* in_sizes, int n_in,
                              void* d_out, int out_size) {
    const float* a       = (const float*)d_in[0];
    const float* b       = (const float*)d_in[1];
    const int*   idx_a   = (const int*)d_in[2];
    const int*   idx_out = (const int*)d_in[3];
    float*       out     = (float*)d_out;

    const int E = in_sizes[2];          // idx_a element count == number of edges

    // Zero the poisoned output buffer (scatter-add target); also pre-dirties
    // out lines into L2 so the subsequent red ops hit.
    int n4 = out_size / 4;              // out_size = M * 128, divisible by 4
    zero_out_kernel<<<(n4 + 255) / 256, 256>>>((float4*)out, n4);

    // Main segmented tensor-product kernel: 8 threads per edge.
    long long threads = (long long)E * 8;
    int grid = (int)((threads + 255) / 256);
    sptp_kernel<<<grid, 256>>>(a, b, idx_a, idx_out, out, E);
}